// round 1
// baseline (speedup 1.0000x reference)
#include <cuda_runtime.h>
#include <cuda_bf16.h>
#include <math_constants.h>

#define B_DIM 64
#define S_DIM 512
#define H_DIM 4096
#define WARPS_PER_BLOCK 16
#define THREADS (WARPS_PER_BLOCK * 32)
#define S_PER_BLOCK 32              // each warp handles 2 s-rows
#define CHUNKS (S_DIM / S_PER_BLOCK) // 16 chunks per batch

// Scratch for energies [B, S] — device global (no cudaMalloc allowed)
__device__ float g_energies[B_DIM * S_DIM];

__global__ __launch_bounds__(THREADS)
void energies_kernel(const float* __restrict__ questions,
                     const float* __restrict__ facts) {
    __shared__ float4 sq[H_DIM / 4];   // 16 KB question row

    const int b      = blockIdx.x / CHUNKS;
    const int schunk = blockIdx.x % CHUNKS;

    // Stage question row for this batch into shared memory (coalesced float4)
    const float4* qv = reinterpret_cast<const float4*>(questions + (size_t)b * H_DIM);
    #pragma unroll
    for (int i = threadIdx.x; i < H_DIM / 4; i += THREADS)
        sq[i] = qv[i];
    __syncthreads();

    const int warp = threadIdx.x >> 5;
    const int lane = threadIdx.x & 31;

    #pragma unroll
    for (int t = 0; t < S_PER_BLOCK / WARPS_PER_BLOCK; ++t) {
        const int s = schunk * S_PER_BLOCK + t * WARPS_PER_BLOCK + warp;
        const float4* fv = reinterpret_cast<const float4*>(
            facts + ((size_t)b * S_DIM + s) * H_DIM);

        // Dot product over H=4096: 32 float4 per lane, 4 accumulators for ILP
        float a0 = 0.f, a1 = 0.f, a2 = 0.f, a3 = 0.f;
        #pragma unroll
        for (int j = 0; j < (H_DIM / 4) / 32; j += 4) {
            float4 f0 = fv[(j + 0) * 32 + lane];
            float4 f1 = fv[(j + 1) * 32 + lane];
            float4 f2 = fv[(j + 2) * 32 + lane];
            float4 f3 = fv[(j + 3) * 32 + lane];
            float4 q0 = sq[(j + 0) * 32 + lane];
            float4 q1 = sq[(j + 1) * 32 + lane];
            float4 q2 = sq[(j + 2) * 32 + lane];
            float4 q3 = sq[(j + 3) * 32 + lane];
            a0 = fmaf(f0.x, q0.x, fmaf(f0.y, q0.y, fmaf(f0.z, q0.z, fmaf(f0.w, q0.w, a0))));
            a1 = fmaf(f1.x, q1.x, fmaf(f1.y, q1.y, fmaf(f1.z, q1.z, fmaf(f1.w, q1.w, a1))));
            a2 = fmaf(f2.x, q2.x, fmaf(f2.y, q2.y, fmaf(f2.z, q2.z, fmaf(f2.w, q2.w, a2))));
            a3 = fmaf(f3.x, q3.x, fmaf(f3.y, q3.y, fmaf(f3.z, q3.z, fmaf(f3.w, q3.w, a3))));
        }
        float acc = (a0 + a1) + (a2 + a3);

        // Warp reduce
        #pragma unroll
        for (int off = 16; off > 0; off >>= 1)
            acc += __shfl_xor_sync(0xffffffffu, acc, off);

        if (lane == 0)
            g_energies[b * S_DIM + s] = acc;
    }
}

__global__ __launch_bounds__(S_DIM)
void softmax_kernel(float* __restrict__ out) {
    const int b   = blockIdx.x;
    const int tid = threadIdx.x;   // 512 threads == S_DIM
    const int warp = tid >> 5;
    const int lane = tid & 31;

    __shared__ float red[WARPS_PER_BLOCK];
    __shared__ float bcast;

    float e = g_energies[b * S_DIM + tid];

    // --- max reduce ---
    float m = e;
    #pragma unroll
    for (int off = 16; off > 0; off >>= 1)
        m = fmaxf(m, __shfl_xor_sync(0xffffffffu, m, off));
    if (lane == 0) red[warp] = m;
    __syncthreads();
    if (tid < 32) {
        float v = (lane < WARPS_PER_BLOCK) ? red[lane] : -CUDART_INF_F;
        #pragma unroll
        for (int off = 16; off > 0; off >>= 1)
            v = fmaxf(v, __shfl_xor_sync(0xffffffffu, v, off));
        if (lane == 0) bcast = v;
    }
    __syncthreads();
    const float row_max = bcast;

    // --- exp + sum reduce ---
    float ex = __expf(e - row_max);
    float s = ex;
    #pragma unroll
    for (int off = 16; off > 0; off >>= 1)
        s += __shfl_xor_sync(0xffffffffu, s, off);
    __syncthreads();   // reuse red[] safely
    if (lane == 0) red[warp] = s;
    __syncthreads();
    if (tid < 32) {
        float v = (lane < WARPS_PER_BLOCK) ? red[lane] : 0.f;
        #pragma unroll
        for (int off = 16; off > 0; off >>= 1)
            v += __shfl_xor_sync(0xffffffffu, v, off);
        if (lane == 0) bcast = v;
    }
    __syncthreads();

    out[b * S_DIM + tid] = ex / bcast;
}

extern "C" void kernel_launch(void* const* d_in, const int* in_sizes, int n_in,
                              void* d_out, int out_size) {
    // Inputs per setup_inputs order: questions [B,H], facts [B,S,H].
    // Guard against ordering by element count (facts is 512x larger).
    const float* questions = (const float*)d_in[0];
    const float* facts     = (const float*)d_in[1];
    if (n_in >= 2 && in_sizes[0] > in_sizes[1]) {
        questions = (const float*)d_in[1];
        facts     = (const float*)d_in[0];
    }
    float* out = (float*)d_out;

    energies_kernel<<<B_DIM * CHUNKS, THREADS>>>(questions, facts);
    softmax_kernel<<<B_DIM, S_DIM>>>(out);
}